// round 1
// baseline (speedup 1.0000x reference)
#include <cuda_runtime.h>
#include <math.h>

#define AG   5
#define BB   2
#define CC   64
#define HH   128
#define WW   128
#define HWSZ (HH*WW)          // 16384 = 2^14
#define CHW  (CC*HWSZ)        // 1048576 = 2^20
#define NIMG (BB*AG)          // 10
#define OC   (3*CC)           // 192
#define IC   (2*CC)           // 128
#define ITERS 2

// scratch (no allocations allowed)
__device__ float g_mean[NIMG*CHW];     // 42 MB
__device__ float g_feats[NIMG*CHW];    // 42 MB (double buffer for feats)
__device__ float g_gx[(size_t)NIMG*OC*HWSZ]; // 126 MB conv outputs (xr|xz|xn)

// ---------------------------------------------------------------------------
// Kernel 1: fused double-bilinear warp + masked mean over j != i
// out[b,i,c,h,w] = (1/(A-1)) * sum_{j!=i} warp(feats[b,j], t[b,i,j])[c,h,w]
// Second resample is a uniform shift -> constant 2x2 outer weights; each outer
// corner is a rotation-grid bilinear gather (4 loads) with zero padding.
// ---------------------------------------------------------------------------
__global__ __launch_bounds__(256) void warp_mean_kernel(
    const float* __restrict__ ext_feats, const float* __restrict__ trans, int it)
{
    const float* feats = (it == 0) ? ext_feats : g_feats;
    int bi = blockIdx.z;
    int b = bi / AG, i = bi % AG;
    int pix = blockIdx.x * 256 + threadIdx.x;   // 64 blocks of 256 = 16384
    int h = pix >> 7, w = pix & (WW - 1);
    int c0 = blockIdx.y * 8;

    float acc[8];
#pragma unroll
    for (int c = 0; c < 8; c++) acc[c] = 0.f;

    for (int j = 0; j < AG; j++) {
        if (j == i) continue;
        const float* tp = trans + (((b*AG + i)*AG + j) << 4);
        float t00 = tp[0], t01 = tp[1], t03 = tp[3];
        float t10 = tp[4], t11 = tp[5], t13 = tp[7];

        // second-stage uniform pixel shift
        float sx = 2.f * t03, sy = -2.f * t13;
        float fsx = floorf(sx), fsy = floorf(sy);
        float axf = sx - fsx, ayf = sy - fsy;
        int qx0 = w + (int)fsx, qy0 = h + (int)fsy;
        float owx[2] = {1.f - axf, axf};
        float owy[2] = {1.f - ayf, ayf};

        int   off[16];
        float wt[16];
#pragma unroll
        for (int a2 = 0; a2 < 2; a2++) {
#pragma unroll
            for (int b2 = 0; b2 < 2; b2++) {
                int p = qy0 + a2, q = qx0 + b2;
                bool outerOK = (p >= 0) && (p < HH) && (q >= 0) && (q < WW);
                float ow = owy[a2] * owx[b2];
                // rotation sample at integer pixel (p,q)
                float gxq = (float)(2*q + 1) * (1.f/(float)WW) - 1.f;
                float gyp = (float)(2*p + 1) * (1.f/(float)HH) - 1.f;
                float px = t00*gxq + t01*gyp;
                float py = t10*gxq + t11*gyp;
                float xs = ((px + 1.f)*(float)WW - 1.f)*0.5f;
                float ys = ((py + 1.f)*(float)HH - 1.f)*0.5f;
                float xs0 = floorf(xs), ys0 = floorf(ys);
                float bx1 = xs - xs0, by1 = ys - ys0;
                int X0 = (int)xs0, Y0 = (int)ys0;
                float iwx[2] = {1.f - bx1, bx1};
                float iwy[2] = {1.f - by1, by1};
                int kb = (a2*2 + b2) * 4;
#pragma unroll
                for (int u = 0; u < 2; u++) {
#pragma unroll
                    for (int v = 0; v < 2; v++) {
                        int Y = Y0 + u, X = X0 + v;
                        bool ok = outerOK && (X >= 0) && (X < WW) && (Y >= 0) && (Y < HH);
                        int Yc = min(max(Y, 0), HH-1);
                        int Xc = min(max(X, 0), WW-1);
                        off[kb + u*2 + v] = Yc*WW + Xc;
                        wt [kb + u*2 + v] = ok ? (ow * iwy[u] * iwx[v]) : 0.f;
                    }
                }
            }
        }

        const float* fb = feats + ((size_t)(b*AG + j)*CC + c0) * HWSZ;
#pragma unroll
        for (int c = 0; c < 8; c++) {
            const float* fp = fb + c*HWSZ;
            float s = 0.f;
#pragma unroll
            for (int k = 0; k < 16; k++) s += wt[k] * fp[off[k]];
            acc[c] += s;
        }
    }

    float* op = g_mean + ((size_t)bi*CC + c0) * HWSZ + pix;
#pragma unroll
    for (int c = 0; c < 8; c++) op[c*HWSZ] = acc[c] * 0.25f;  // /(A-1)
}

// ---------------------------------------------------------------------------
// Kernel 2: direct 3x3 conv, 128->192, SAME zero pad, bias bx.
// Block: 256 thr (16x16), output tile 32x32, 8 output channels. Input = cat
// (feats first 64 ch, mean next 64 ch). Writes g_gx[img, oc, h, w].
// ---------------------------------------------------------------------------
#define OCG 8
#define TILE 32

__global__ __launch_bounds__(256) void conv_kernel(
    const float* __restrict__ ext_feats,
    const float* __restrict__ wx, const float* __restrict__ bxv, int it)
{
    __shared__ float s_w[OCG*IC*9];      // 36864 B
    __shared__ float s_in[2][34*35];     // 9520 B, stride 35 -> conflict-free

    const float* featp = (it == 0) ? ext_feats : g_feats;
    int img = blockIdx.z;
    int oc0 = blockIdx.y * OCG;
    int tX = (blockIdx.x & 3) * TILE;
    int tY = (blockIdx.x >> 2) * TILE;
    int tid = threadIdx.x;
    int tx = tid & 15, ty = tid >> 4;

    // stage weights: wx layout [oc][cin][3][3], contiguous slice for this ocg
    for (int idx = tid; idx < OCG*IC*9; idx += 256)
        s_w[idx] = wx[(size_t)oc0 * IC * 9 + idx];

    float acc[4][OCG];
#pragma unroll
    for (int p = 0; p < 4; p++)
#pragma unroll
        for (int o = 0; o < OCG; o++) acc[p][o] = bxv[oc0 + o];

    const float* f0 = featp + (size_t)img * CHW;
    const float* m0 = g_mean + (size_t)img * CHW;
    int ox = tX - 1, oy = tY - 1;

    for (int cin0 = 0; cin0 < IC; cin0 += 2) {
        __syncthreads();
        for (int idx = tid; idx < 2*34*34; idx += 256) {
            int cl = idx / 1156;
            int r  = (idx - cl*1156) / 34;
            int cc2 = idx - cl*1156 - r*34;
            int gy = oy + r, gx2 = ox + cc2;
            int cin = cin0 + cl;
            const float* sp = (cin < CC) ? (f0 + (size_t)cin * HWSZ)
                                         : (m0 + (size_t)(cin - CC) * HWSZ);
            float v = 0.f;
            if (gy >= 0 && gy < HH && gx2 >= 0 && gx2 < WW)
                v = sp[gy*WW + gx2];
            s_in[cl][r*35 + cc2] = v;
        }
        __syncthreads();
#pragma unroll
        for (int cl = 0; cl < 2; cl++) {
            float xv[16];
#pragma unroll
            for (int yy = 0; yy < 4; yy++)
#pragma unroll
                for (int xx = 0; xx < 4; xx++)
                    xv[yy*4 + xx] = s_in[cl][(ty*2 + yy)*35 + tx*2 + xx];
            int wb = (cin0 + cl) * 9;
#pragma unroll
            for (int o = 0; o < OCG; o++) {
                const float* wp = &s_w[o*IC*9 + wb];
#pragma unroll
                for (int ky = 0; ky < 3; ky++) {
#pragma unroll
                    for (int kx = 0; kx < 3; kx++) {
                        float wv = wp[ky*3 + kx];
                        acc[0][o] += wv * xv[(ky  )*4 + kx    ];
                        acc[1][o] += wv * xv[(ky  )*4 + kx + 1];
                        acc[2][o] += wv * xv[(ky+1)*4 + kx    ];
                        acc[3][o] += wv * xv[(ky+1)*4 + kx + 1];
                    }
                }
            }
        }
    }

    int hb = tY + ty*2, wb2 = tX + tx*2;
#pragma unroll
    for (int o = 0; o < OCG; o++) {
        float* op = g_gx + ((size_t)img*OC + oc0 + o) * HWSZ;
#pragma unroll
        for (int yy = 0; yy < 2; yy++) {
            float2 v = make_float2(acc[yy*2 + 0][o], acc[yy*2 + 1][o]);
            *(float2*)(op + (hb + yy)*WW + wb2) = v;
        }
    }
}

// ---------------------------------------------------------------------------
// Kernel 3: GRU gate elementwise (h0 = 0):
// r=sig(xr+br), z=sig(xz+bz), n=tanh(xn + r*bn), h'=(1-z)*n
// ---------------------------------------------------------------------------
__global__ __launch_bounds__(256) void gru_kernel(
    const float* __restrict__ bh, float* __restrict__ ext_out, int last)
{
    int idx = blockIdx.x * 256 + threadIdx.x;     // NIMG*CHW = 10485760 exact
    if (idx >= NIMG*CHW) return;
    int img = idx >> 20;               // / CHW
    int rem = idx & (CHW - 1);
    int c = rem >> 14;                 // / HW
    int p = rem & (HWSZ - 1);
    const float* base = g_gx + (size_t)img * OC * HWSZ;
    float xr = base[(size_t)(c        )*HWSZ + p];
    float xz = base[(size_t)(c +   CC )*HWSZ + p];
    float xn = base[(size_t)(c + 2*CC )*HWSZ + p];
    float r = 1.f / (1.f + expf(-(xr + bh[c])));
    float z = 1.f / (1.f + expf(-(xz + bh[c + CC])));
    float n = tanhf(xn + r * bh[c + 2*CC]);
    float hv = (1.f - z) * n;
    float* dst = last ? ext_out : g_feats;
    dst[idx] = hv;
}

// ---------------------------------------------------------------------------
extern "C" void kernel_launch(void* const* d_in, const int* in_sizes, int n_in,
                              void* d_out, int out_size)
{
    const float* feats = (const float*)d_in[0];
    const float* trans = (const float*)d_in[1];
    const float* wx    = (const float*)d_in[2];
    // d_in[3] = wh : unused (h0 = 0 -> hidden conv vanishes; only bh survives)
    const float* bx    = (const float*)d_in[4];
    const float* bh    = (const float*)d_in[5];
    float* out = (float*)d_out;

    for (int it = 0; it < ITERS; it++) {
        warp_mean_kernel<<<dim3(HWSZ/256, CC/8, NIMG), 256>>>(feats, trans, it);
        conv_kernel<<<dim3(16, OC/OCG, NIMG), 256>>>(feats, wx, bx, it);
        gru_kernel<<<(NIMG*CHW)/256, 256>>>(bh, out, (it == ITERS-1) ? 1 : 0);
    }
}

// round 5
// speedup vs baseline: 2.3185x; 2.3185x over previous
#include <cuda_runtime.h>
#include <cuda_bf16.h>
#include <math.h>
#include <stdint.h>

#define AG   5
#define BB   2
#define CC   64
#define HH   128
#define WW   128
#define HWSZ (HH*WW)          // 16384
#define CHW  (CC*HWSZ)        // 1048576
#define NIMG (BB*AG)          // 10
#define OC   192
#define IC   128
#define ITERS 2
#define PW   130              // padded H/W
#define PPIX (PW*PW)          // 16900

// ---------------- device scratch (no allocs allowed) ----------------
__device__ float g_mean[NIMG*CHW];                         // 42 MB  NCHW mean
__device__ float g_feats[NIMG*CHW];                        // 42 MB  NCHW feats double-buffer
__device__ __nv_bfloat16 g_X[2][NIMG][(size_t)PPIX*IC];    // 86.5 MB padded NHWC (hi,lo)
__device__ __nv_bfloat16 g_W[2][9][OC*IC];                 // packed weights (hi,lo)[tap][oc][cin]

// ---------------- warp-MMA helpers (sm_80-class ISA, compiles for sm_103) ---
__device__ __forceinline__ uint32_t smem_u32(const void* p) {
    uint32_t a;
    asm("{ .reg .u64 t; cvta.to.shared.u64 t, %1; cvt.u32.u64 %0, t; }" : "=r"(a) : "l"(p));
    return a;
}
__device__ __forceinline__ void ldsm4(uint32_t* r, uint32_t addr) {
    asm volatile("ldmatrix.sync.aligned.m8n8.x4.shared.b16 {%0,%1,%2,%3}, [%4];"
        : "=r"(r[0]), "=r"(r[1]), "=r"(r[2]), "=r"(r[3]) : "r"(addr));
}
__device__ __forceinline__ void mma16816(float* c, const uint32_t* a, const uint32_t* b) {
    asm volatile("mma.sync.aligned.m16n8k16.row.col.f32.bf16.bf16.f32 "
        "{%0,%1,%2,%3}, {%4,%5,%6,%7}, {%8,%9}, {%0,%1,%2,%3};"
        : "+f"(c[0]), "+f"(c[1]), "+f"(c[2]), "+f"(c[3])
        : "r"(a[0]), "r"(a[1]), "r"(a[2]), "r"(a[3]), "r"(b[0]), "r"(b[1]));
}

// smem geometry for conv kernel
#define ASTRIDE   272                 // bytes per pixel row (128 bf16 + 8 pad)
#define A_SPLIT   35360               // 130 * 272
#define OFF_B     70720               // 2 * A_SPLIT
#define B_SPLIT   52224               // 192 * 272
#define SMEM_CONV 175168              // OFF_B + 2*B_SPLIT
#define GRU_STRIDE 193                // floats per px row in epilogue buffer

// ---------------------------------------------------------------------------
// Kernel 1: fused double-bilinear warp + masked mean over j != i
// ---------------------------------------------------------------------------
__global__ __launch_bounds__(256) void warp_mean_kernel(
    const float* __restrict__ ext_feats, const float* __restrict__ trans, int it)
{
    const float* feats = (it == 0) ? ext_feats : g_feats;
    int bi = blockIdx.z;
    int b = bi / AG, i = bi % AG;
    int pix = blockIdx.x * 256 + threadIdx.x;
    int h = pix >> 7, w = pix & (WW - 1);
    int c0 = blockIdx.y * 8;

    float acc[8];
#pragma unroll
    for (int c = 0; c < 8; c++) acc[c] = 0.f;

    for (int j = 0; j < AG; j++) {
        if (j == i) continue;
        const float* tp = trans + (((b*AG + i)*AG + j) << 4);
        float t00 = tp[0], t01 = tp[1], t03 = tp[3];
        float t10 = tp[4], t11 = tp[5], t13 = tp[7];

        float sx = 2.f * t03, sy = -2.f * t13;
        float fsx = floorf(sx), fsy = floorf(sy);
        float axf = sx - fsx, ayf = sy - fsy;
        int qx0 = w + (int)fsx, qy0 = h + (int)fsy;
        float owx[2] = {1.f - axf, axf};
        float owy[2] = {1.f - ayf, ayf};

        int   off[16];
        float wt[16];
#pragma unroll
        for (int a2 = 0; a2 < 2; a2++) {
#pragma unroll
            for (int b2 = 0; b2 < 2; b2++) {
                int p = qy0 + a2, q = qx0 + b2;
                bool outerOK = (p >= 0) && (p < HH) && (q >= 0) && (q < WW);
                float ow = owy[a2] * owx[b2];
                float gxq = (float)(2*q + 1) * (1.f/(float)WW) - 1.f;
                float gyp = (float)(2*p + 1) * (1.f/(float)HH) - 1.f;
                float px = t00*gxq + t01*gyp;
                float py = t10*gxq + t11*gyp;
                float xs = ((px + 1.f)*(float)WW - 1.f)*0.5f;
                float ys = ((py + 1.f)*(float)HH - 1.f)*0.5f;
                float xs0 = floorf(xs), ys0 = floorf(ys);
                float bx1 = xs - xs0, by1 = ys - ys0;
                int X0 = (int)xs0, Y0 = (int)ys0;
                float iwx[2] = {1.f - bx1, bx1};
                float iwy[2] = {1.f - by1, by1};
                int kb = (a2*2 + b2) * 4;
#pragma unroll
                for (int u = 0; u < 2; u++) {
#pragma unroll
                    for (int v = 0; v < 2; v++) {
                        int Y = Y0 + u, X = X0 + v;
                        bool ok = outerOK && (X >= 0) && (X < WW) && (Y >= 0) && (Y < HH);
                        int Yc = min(max(Y, 0), HH-1);
                        int Xc = min(max(X, 0), WW-1);
                        off[kb + u*2 + v] = Yc*WW + Xc;
                        wt [kb + u*2 + v] = ok ? (ow * iwy[u] * iwx[v]) : 0.f;
                    }
                }
            }
        }

        const float* fb = feats + ((size_t)(b*AG + j)*CC + c0) * HWSZ;
#pragma unroll
        for (int c = 0; c < 8; c++) {
            const float* fp = fb + c*HWSZ;
            float s = 0.f;
#pragma unroll
            for (int k = 0; k < 16; k++) s += wt[k] * fp[off[k]];
            acc[c] += s;
        }
    }

    float* op = g_mean + ((size_t)bi*CC + c0) * HWSZ + pix;
#pragma unroll
    for (int c = 0; c < 8; c++) op[c*HWSZ] = acc[c] * 0.25f;
}

// ---------------------------------------------------------------------------
// Weight prepack: wx[oc][cin][3][3] fp32 -> g_W[split][tap][oc][cin] bf16
// ---------------------------------------------------------------------------
__global__ __launch_bounds__(256) void wprep_kernel(const float* __restrict__ wx)
{
    int idx = blockIdx.x * 256 + threadIdx.x;
    if (idx >= 2*9*OC*IC) return;
    int s   = idx / (9*OC*IC);
    int r1  = idx % (9*OC*IC);
    int tap = r1 / (OC*IC);
    int r2  = r1 % (OC*IC);
    int oc  = r2 / IC;
    int cin = r2 % IC;
    float v = wx[(size_t)(oc*IC + cin)*9 + tap];
    __nv_bfloat16 hi = __float2bfloat16_rn(v);
    __nv_bfloat16 o  = (s == 0) ? hi : __float2bfloat16_rn(v - __bfloat162float(hi));
    g_W[s][tap][oc*IC + cin] = o;
}

// ---------------------------------------------------------------------------
// Zero the 1-px border of the padded NHWC buffer
// ---------------------------------------------------------------------------
__global__ void border_kernel()
{
    int img = blockIdx.x;
    uint4 z = make_uint4(0,0,0,0);
    for (int p = threadIdx.x; p < PPIX; p += blockDim.x) {
        int r = p / PW, c = p % PW;
        if (r == 0 || r == PW-1 || c == 0 || c == PW-1) {
            uint4* d0 = (uint4*)&g_X[0][img][(size_t)p*IC];
            uint4* d1 = (uint4*)&g_X[1][img][(size_t)p*IC];
#pragma unroll
            for (int k = 0; k < 16; k++) { d0[k] = z; d1[k] = z; }
        }
    }
}

// ---------------------------------------------------------------------------
// Pack: cat(feats, mean) NCHW fp32 -> padded NHWC bf16 hi/lo (interior only)
// ---------------------------------------------------------------------------
__global__ __launch_bounds__(256) void pack_kernel(const float* __restrict__ ext_feats, int it)
{
    const float* feats = (it == 0) ? ext_feats : g_feats;
    __shared__ float s[IC][33];
    int img = blockIdx.z, h = blockIdx.y, w0 = blockIdx.x * 32;
    int tid = threadIdx.x;
    const float* f0 = feats + (size_t)img * CHW;
    const float* m0 = g_mean + (size_t)img * CHW;
#pragma unroll
    for (int pass = 0; pass < 16; pass++) {
        int c = pass*8 + (tid >> 5);
        const float* sp = (c < CC) ? f0 + (size_t)c*HWSZ : m0 + (size_t)(c - CC)*HWSZ;
        s[c][tid & 31] = sp[h*WW + w0 + (tid & 31)];
    }
    __syncthreads();
    int px = tid >> 3;
    int c0 = (tid & 7) * 16;
    int w  = w0 + px;
    size_t base = ((size_t)(h+1)*PW + (w+1))*IC + c0;
    uint32_t uh[8], ul[8];
#pragma unroll
    for (int k = 0; k < 8; k++) {
        float v0 = s[c0 + 2*k][px], v1 = s[c0 + 2*k + 1][px];
        __nv_bfloat16 h0 = __float2bfloat16_rn(v0);
        __nv_bfloat16 h1 = __float2bfloat16_rn(v1);
        __nv_bfloat16 l0 = __float2bfloat16_rn(v0 - __bfloat162float(h0));
        __nv_bfloat16 l1 = __float2bfloat16_rn(v1 - __bfloat162float(h1));
        uh[k] = ((uint32_t)__bfloat16_as_ushort(h1) << 16) | __bfloat16_as_ushort(h0);
        ul[k] = ((uint32_t)__bfloat16_as_ushort(l1) << 16) | __bfloat16_as_ushort(l0);
    }
    uint4* dh = (uint4*)&g_X[0][img][base];
    uint4* dl = (uint4*)&g_X[1][img][base];
    dh[0] = make_uint4(uh[0], uh[1], uh[2], uh[3]);
    dh[1] = make_uint4(uh[4], uh[5], uh[6], uh[7]);
    dl[0] = make_uint4(ul[0], ul[1], ul[2], ul[3]);
    dl[1] = make_uint4(ul[4], ul[5], ul[6], ul[7]);
}

// ---------------------------------------------------------------------------
// Conv+GRU via mma.sync (HMMA bf16, 3-term hi/lo split).
// CTA = one image row: M=128 px, N=192 oc, K=9 taps x 128 cin.
// 8 warps = 4(M) x 2(N); warp tile 32 x 96 -> acc[2][12][4].
// A smem: 130 px x 128 cin (hi+lo), row stride 272B. 3 kx taps share A.
// Epilogue: accs -> f32 smem -> fused GRU -> NCHW gmem.
// ---------------------------------------------------------------------------
__global__ __launch_bounds__(256, 1) void conv_mma_kernel(
    const float* __restrict__ bxv, const float* __restrict__ bhv,
    float* __restrict__ ext_out, int last)
{
    extern __shared__ char smem[];
    uint32_t sb = smem_u32(smem);
    int tid = threadIdx.x, wid = tid >> 5, lane = tid & 31;
    int img = blockIdx.y, h = blockIdx.x;
    int warp_m = wid & 3, warp_n = wid >> 2;

    float acc[2][12][4];
#pragma unroll
    for (int mi = 0; mi < 2; mi++)
#pragma unroll
        for (int nj = 0; nj < 12; nj++)
#pragma unroll
            for (int k = 0; k < 4; k++) acc[mi][nj][k] = 0.f;

    // per-lane ldmatrix base addresses
    uint32_t aLane = sb + (uint32_t)(warp_m*32 + (lane & 15))*ASTRIDE + ((lane >> 4)*8)*2;
    uint32_t bLane = sb + OFF_B
                   + (uint32_t)(warp_n*96 + (lane & 7) + ((lane >> 4) << 3))*ASTRIDE
                   + (((lane >> 3) & 1)*8)*2;

    for (int ky = 0; ky < 3; ky++) {
        __syncthreads();     // previous tap's mma consumers done before A overwrite
        // stage A row (h+ky): 130 px x 128 cin, hi & lo
#pragma unroll
        for (int s = 0; s < 2; s++) {
            const __nv_bfloat16* src = &g_X[s][img][((size_t)(h + ky)*PW)*IC];
            char* dst = smem + s*A_SPLIT;
            for (int idx = tid; idx < 130*16; idx += 256) {
                int p = idx >> 4, cg = idx & 15;
                uint4 v = *(const uint4*)(src + p*IC + cg*8);
                *(uint4*)(dst + p*ASTRIDE + cg*16) = v;
            }
        }
        for (int kx = 0; kx < 3; kx++) {
            __syncthreads();  // A ready / previous B consumers done
            // stage B tap (hi & lo): 192 oc x 128 cin
            {
                int tap = ky*3 + kx;
#pragma unroll
                for (int s = 0; s < 2; s++) {
                    const __nv_bfloat16* src = &g_W[s][tap][0];
                    char* dst = smem + OFF_B + s*B_SPLIT;
                    for (int idx = tid; idx < 192*16; idx += 256) {
                        int p = idx >> 4, cg = idx & 15;
                        uint4 v = *(const uint4*)(src + p*IC + cg*8);
                        *(uint4*)(dst + p*ASTRIDE + cg*16) = v;
                    }
                }
            }
            __syncthreads();

            uint32_t aBase = aLane + kx*ASTRIDE;
#pragma unroll
            for (int ks = 0; ks < 8; ks++) {
                uint32_t ah[2][4], al[2][4], bq[6][4];
                ldsm4(ah[0], aBase + ks*32);
                ldsm4(ah[1], aBase + 16*ASTRIDE + ks*32);
                ldsm4(al[0], aBase + A_SPLIT + ks*32);
                ldsm4(al[1], aBase + A_SPLIT + 16*ASTRIDE + ks*32);
#pragma unroll
                for (int nt = 0; nt < 6; nt++)
                    ldsm4(bq[nt], bLane + nt*16*ASTRIDE + ks*32);
#pragma unroll
                for (int mi = 0; mi < 2; mi++)
#pragma unroll
                    for (int nj = 0; nj < 12; nj++)
                        mma16816(acc[mi][nj], ah[mi], &bq[nj >> 1][(nj & 1)*2]);
#pragma unroll
                for (int mi = 0; mi < 2; mi++)
#pragma unroll
                    for (int nj = 0; nj < 12; nj++)
                        mma16816(acc[mi][nj], al[mi], &bq[nj >> 1][(nj & 1)*2]);
#pragma unroll
                for (int nt = 0; nt < 6; nt++)
                    ldsm4(bq[nt], bLane + B_SPLIT + nt*16*ASTRIDE + ks*32);
#pragma unroll
                for (int mi = 0; mi < 2; mi++)
#pragma unroll
                    for (int nj = 0; nj < 12; nj++)
                        mma16816(acc[mi][nj], ah[mi], &bq[nj >> 1][(nj & 1)*2]);
            }
        }
    }

    // ---- epilogue: accs -> f32 smem [128 px][192 oc] stride 193, fused GRU ----
    __syncthreads();
    {
        float* buf = (float*)smem;
        int r0 = lane >> 2, c0 = (lane & 3)*2;
#pragma unroll
        for (int mi = 0; mi < 2; mi++) {
#pragma unroll
            for (int nj = 0; nj < 12; nj++) {
                int px = warp_m*32 + mi*16 + r0;
                int oc = warp_n*96 + nj*8 + c0;
                float* s0 = buf + px*GRU_STRIDE + oc;
                s0[0] = acc[mi][nj][0];
                s0[1] = acc[mi][nj][1];
                float* s1 = buf + (px + 8)*GRU_STRIDE + oc;
                s1[0] = acc[mi][nj][2];
                s1[1] = acc[mi][nj][3];
            }
        }
    }
    __syncthreads();
    {
        const float* buf = (const float*)smem;
        int px = tid & 127, half = tid >> 7;
        const float* row = buf + px*GRU_STRIDE;
        float* dst = (last ? ext_out : g_feats) + (size_t)img*CHW + h*WW + px;
#pragma unroll
        for (int k = 0; k < 32; k++) {
            int c = half*32 + k;
            float xr = row[c]        + bxv[c]        + bhv[c];
            float xz = row[64 + c]   + bxv[64 + c]   + bhv[64 + c];
            float xn = row[128 + c]  + bxv[128 + c];
            float rg = 1.f / (1.f + expf(-xr));
            float zg = 1.f / (1.f + expf(-xz));
            float ng = tanhf(xn + rg * bhv[128 + c]);
            dst[(size_t)c * HWSZ] = (1.f - zg) * ng;
        }
    }
}

// ---------------------------------------------------------------------------
extern "C" void kernel_launch(void* const* d_in, const int* in_sizes, int n_in,
                              void* d_out, int out_size)
{
    const float* feats = (const float*)d_in[0];
    const float* trans = (const float*)d_in[1];
    const float* wx    = (const float*)d_in[2];
    // d_in[3] = wh : unused (h0 = 0)
    const float* bx    = (const float*)d_in[4];
    const float* bh    = (const float*)d_in[5];
    float* out = (float*)d_out;

    cudaFuncSetAttribute(conv_mma_kernel,
                         cudaFuncAttributeMaxDynamicSharedMemorySize, SMEM_CONV);

    wprep_kernel<<<(2*9*OC*IC + 255)/256, 256>>>(wx);
    border_kernel<<<NIMG, 256>>>();

    for (int it = 0; it < ITERS; it++) {
        warp_mean_kernel<<<dim3(HWSZ/256, CC/8, NIMG), 256>>>(feats, trans, it);
        pack_kernel<<<dim3(WW/32, HH, NIMG), 256>>>(feats, it);
        conv_mma_kernel<<<dim3(HH, NIMG), 256, SMEM_CONV>>>(
            bx, bh, out, (it == ITERS-1) ? 1 : 0);
    }
}

// round 9
// speedup vs baseline: 3.1228x; 1.3469x over previous
#include <cuda_runtime.h>
#include <cuda_bf16.h>
#include <math.h>
#include <stdint.h>

#define AG   5
#define BB   2
#define CC   64
#define HH   128
#define WW   128
#define HWSZ (HH*WW)          // 16384
#define CHW  (CC*HWSZ)        // 1048576
#define NIMG (BB*AG)          // 10
#define OC   192
#define IC   128
#define ITERS 2
#define PW   130              // padded H/W
#define PPIX (PW*PW)          // 16900

// ---------------- device scratch (no allocs allowed) ----------------
// g_X[split][buf][img][pix*128ch] : padded NHWC bf16. ch0-63 = feats, ch64-127 = mean.
__device__ __nv_bfloat16 g_X[2][2][NIMG][(size_t)PPIX*IC];   // 173 MB
__device__ __nv_bfloat16 g_W[2][9][OC*IC];                   // packed weights (hi,lo)

// ---------------- warp-MMA helpers ----------------
__device__ __forceinline__ uint32_t smem_u32(const void* p) {
    uint32_t a;
    asm("{ .reg .u64 t; cvta.to.shared.u64 t, %1; cvt.u32.u64 %0, t; }" : "=r"(a) : "l"(p));
    return a;
}
__device__ __forceinline__ void ldsm4(uint32_t* r, uint32_t addr) {
    asm volatile("ldmatrix.sync.aligned.m8n8.x4.shared.b16 {%0,%1,%2,%3}, [%4];"
        : "=r"(r[0]), "=r"(r[1]), "=r"(r[2]), "=r"(r[3]) : "r"(addr));
}
__device__ __forceinline__ void mma16816(float* c, const uint32_t* a, const uint32_t* b) {
    asm volatile("mma.sync.aligned.m16n8k16.row.col.f32.bf16.bf16.f32 "
        "{%0,%1,%2,%3}, {%4,%5,%6,%7}, {%8,%9}, {%0,%1,%2,%3};"
        : "+f"(c[0]), "+f"(c[1]), "+f"(c[2]), "+f"(c[3])
        : "r"(a[0]), "r"(a[1]), "r"(a[2]), "r"(a[3]), "r"(b[0]), "r"(b[1]));
}

// smem geometry for conv kernel
#define ASTRIDE   272
#define A_SPLIT   35360               // 130 * 272
#define OFF_B     70720
#define B_SPLIT   52224               // 192 * 272
#define SMEM_CONV 175168
#define GRU_STRIDE 193

// ---------------------------------------------------------------------------
// Kernel 1: warp-per-pixel fused double-bilinear warp + masked mean (NHWC).
// Lane = channel pair. Gather point = one 128B line per split -> coalesced.
// Writes mean directly into g_X[.][buf] channels 64-127 as bf16 hi/lo.
// ---------------------------------------------------------------------------
__global__ __launch_bounds__(256) void warp_mean_kernel(
    const float* __restrict__ trans, int buf)
{
    int tid = threadIdx.x, wid = tid >> 5, lane = tid & 31;
    int img = blockIdx.z;
    int b = img / AG, i = img % AG;
    int w = blockIdx.x * 4 + (wid & 3);
    int h = blockIdx.y * 2 + (wid >> 2);

    float2 acc = make_float2(0.f, 0.f);

    for (int j = 0; j < AG; j++) {
        if (j == i) continue;
        // gather from NEIGHBOR j's image (bug fix vs round 6)
        const uint32_t* Phi = (const uint32_t*)&g_X[0][buf][b*AG + j][0];
        const uint32_t* Plo = (const uint32_t*)&g_X[1][buf][b*AG + j][0];

        const float* tp = trans + (((b*AG + i)*AG + j) << 4);
        float t00 = tp[0], t01 = tp[1], t03 = tp[3];
        float t10 = tp[4], t11 = tp[5], t13 = tp[7];

        float sx = 2.f * t03, sy = -2.f * t13;
        float fsx = floorf(sx), fsy = floorf(sy);
        float axf = sx - fsx, ayf = sy - fsy;
        int qx0 = w + (int)fsx, qy0 = h + (int)fsy;

        // lane k (0-15, duplicated on 16-31) computes gather point k
        int k  = lane & 15;
        int a2 = (k >> 3) & 1, b2 = (k >> 2) & 1, u = (k >> 1) & 1, v = k & 1;
        int p = qy0 + a2, q = qx0 + b2;
        bool outerOK = (p >= 0) && (p < HH) && (q >= 0) && (q < WW);
        float ow = (a2 ? ayf : 1.f - ayf) * (b2 ? axf : 1.f - axf);
        float gxq = (float)(2*q + 1) * (1.f/(float)WW) - 1.f;
        float gyp = (float)(2*p + 1) * (1.f/(float)HH) - 1.f;
        float px = t00*gxq + t01*gyp;
        float py = t10*gxq + t11*gyp;
        float xs = ((px + 1.f)*(float)WW - 1.f)*0.5f;
        float ys = ((py + 1.f)*(float)HH - 1.f)*0.5f;
        float xs0 = floorf(xs), ys0 = floorf(ys);
        float bx1 = xs - xs0, by1 = ys - ys0;
        int X = (int)xs0 + v, Y = (int)ys0 + u;
        bool ok = outerOK && (X >= 0) && (X < WW) && (Y >= 0) && (Y < HH);
        float iw = (u ? by1 : 1.f - by1) * (v ? bx1 : 1.f - bx1);
        float wt = ok ? (ow * iw) : 0.f;
        int Yc = min(max(Y, 0), HH-1), Xc = min(max(X, 0), WW-1);
        int offw = ((Yc + 1)*PW + (Xc + 1)) * 64;   // word offset of pixel (64 words/split)

#pragma unroll
        for (int kk = 0; kk < 16; kk++) {
            float wtk = __shfl_sync(0xffffffffu, wt, kk);
            int   ofk = __shfl_sync(0xffffffffu, offw, kk);
            if (wtk != 0.f) {
                uint32_t hw = Phi[ofk + lane];
                uint32_t lw = Plo[ofk + lane];
                float2 hf = __bfloat1622float2(*(__nv_bfloat162*)&hw);
                float2 lf = __bfloat1622float2(*(__nv_bfloat162*)&lw);
                acc.x = fmaf(wtk, hf.x + lf.x, acc.x);
                acc.y = fmaf(wtk, hf.y + lf.y, acc.y);
            }
        }
    }

    acc.x *= 0.25f; acc.y *= 0.25f;
    __nv_bfloat162 hb = __floats2bfloat162_rn(acc.x, acc.y);
    float2 hf = __bfloat1622float2(hb);
    __nv_bfloat162 lb = __floats2bfloat162_rn(acc.x - hf.x, acc.y - hf.y);
    int dpix = ((h + 1)*PW + (w + 1)) * 64 + 32 + lane;   // mean half: words 32-63
    ((uint32_t*)&g_X[0][buf][img][0])[dpix] = *(uint32_t*)&hb;
    ((uint32_t*)&g_X[1][buf][img][0])[dpix] = *(uint32_t*)&lb;
}

// ---------------------------------------------------------------------------
// Weight prepack: wx[oc][cin][3][3] fp32 -> g_W[split][tap][oc][cin] bf16
// ---------------------------------------------------------------------------
__global__ __launch_bounds__(256) void wprep_kernel(const float* __restrict__ wx)
{
    int idx = blockIdx.x * 256 + threadIdx.x;
    if (idx >= 2*9*OC*IC) return;
    int s   = idx / (9*OC*IC);
    int r1  = idx % (9*OC*IC);
    int tap = r1 / (OC*IC);
    int r2  = r1 % (OC*IC);
    int oc  = r2 / IC;
    int cin = r2 % IC;
    float v = wx[(size_t)(oc*IC + cin)*9 + tap];
    __nv_bfloat16 hi = __float2bfloat16_rn(v);
    __nv_bfloat16 o  = (s == 0) ? hi : __float2bfloat16_rn(v - __bfloat162float(hi));
    g_W[s][tap][oc*IC + cin] = o;
}

// ---------------------------------------------------------------------------
// Zero the 1-px border of both g_X buffers (all 128 ch, both splits)
// ---------------------------------------------------------------------------
__global__ void border_kernel()
{
    int img = blockIdx.x;
    uint4 z = make_uint4(0,0,0,0);
    for (int p = threadIdx.x; p < PPIX; p += blockDim.x) {
        int r = p / PW, c = p % PW;
        if (r == 0 || r == PW-1 || c == 0 || c == PW-1) {
#pragma unroll
            for (int s = 0; s < 2; s++)
#pragma unroll
                for (int bf = 0; bf < 2; bf++) {
                    uint4* d = (uint4*)&g_X[s][bf][img][(size_t)p*IC];
#pragma unroll
                    for (int k2 = 0; k2 < 16; k2++) d[k2] = z;
                }
        }
    }
}

// ---------------------------------------------------------------------------
// One-time pack of input feats NCHW fp32 -> g_X[.][0] feats half (ch 0-63)
// ---------------------------------------------------------------------------
__global__ __launch_bounds__(256) void pack0_kernel(const float* __restrict__ feats)
{
    __shared__ float s[CC][33];
    int img = blockIdx.z, h = blockIdx.y, w0 = blockIdx.x * 32;
    int tid = threadIdx.x;
    const float* f0 = feats + (size_t)img * CHW;
#pragma unroll
    for (int pass = 0; pass < 8; pass++) {
        int c = pass*8 + (tid >> 5);
        s[c][tid & 31] = f0[(size_t)c*HWSZ + h*WW + w0 + (tid & 31)];
    }
    __syncthreads();
    int px = tid >> 3;
    int c0 = (tid & 7) * 8;
    uint32_t uh[4], ul[4];
#pragma unroll
    for (int k = 0; k < 4; k++) {
        float v0 = s[c0 + 2*k][px], v1 = s[c0 + 2*k + 1][px];
        __nv_bfloat162 hb = __floats2bfloat162_rn(v0, v1);
        float2 hf = __bfloat1622float2(hb);
        __nv_bfloat162 lb = __floats2bfloat162_rn(v0 - hf.x, v1 - hf.y);
        uh[k] = *(uint32_t*)&hb;
        ul[k] = *(uint32_t*)&lb;
    }
    int wordb = ((h + 1)*PW + (w0 + px + 1)) * 64 + (c0 >> 1);
    *(uint4*)((uint32_t*)&g_X[0][0][img][0] + wordb) = make_uint4(uh[0], uh[1], uh[2], uh[3]);
    *(uint4*)((uint32_t*)&g_X[1][0][img][0] + wordb) = make_uint4(ul[0], ul[1], ul[2], ul[3]);
}

// ---------------------------------------------------------------------------
// Conv+GRU via mma.sync (HMMA bf16, 3-term hi/lo split).
// CTA = one image row: M=128 px, N=192 oc, K=9 taps x 128 cin.
// Epilogue: fused GRU -> ext_out (last) or g_X[.][buf^1] feats half NHWC hi/lo.
// ---------------------------------------------------------------------------
__global__ __launch_bounds__(256, 1) void conv_mma_kernel(
    const float* __restrict__ bxv, const float* __restrict__ bhv,
    float* __restrict__ ext_out, int buf, int last)
{
    extern __shared__ char smem[];
    uint32_t sb = smem_u32(smem);
    int tid = threadIdx.x, wid = tid >> 5, lane = tid & 31;
    int img = blockIdx.y, h = blockIdx.x;
    int warp_m = wid & 3, warp_n = wid >> 2;

    float acc[2][12][4];
#pragma unroll
    for (int mi = 0; mi < 2; mi++)
#pragma unroll
        for (int nj = 0; nj < 12; nj++)
#pragma unroll
            for (int k = 0; k < 4; k++) acc[mi][nj][k] = 0.f;

    uint32_t aLane = sb + (uint32_t)(warp_m*32 + (lane & 15))*ASTRIDE + ((lane >> 4)*8)*2;
    uint32_t bLane = sb + OFF_B
                   + (uint32_t)(warp_n*96 + (lane & 7) + ((lane >> 4) << 3))*ASTRIDE
                   + (((lane >> 3) & 1)*8)*2;

    for (int ky = 0; ky < 3; ky++) {
        __syncthreads();
#pragma unroll
        for (int s = 0; s < 2; s++) {
            const __nv_bfloat16* src = &g_X[s][buf][img][((size_t)(h + ky)*PW)*IC];
            char* dst = smem + s*A_SPLIT;
            for (int idx = tid; idx < 130*16; idx += 256) {
                int p = idx >> 4, cg = idx & 15;
                uint4 v = *(const uint4*)(src + p*IC + cg*8);
                *(uint4*)(dst + p*ASTRIDE + cg*16) = v;
            }
        }
        for (int kx = 0; kx < 3; kx++) {
            __syncthreads();
            {
                int tap = ky*3 + kx;
#pragma unroll
                for (int s = 0; s < 2; s++) {
                    const __nv_bfloat16* src = &g_W[s][tap][0];
                    char* dst = smem + OFF_B + s*B_SPLIT;
                    for (int idx = tid; idx < 192*16; idx += 256) {
                        int p = idx >> 4, cg = idx & 15;
                        uint4 v = *(const uint4*)(src + p*IC + cg*8);
                        *(uint4*)(dst + p*ASTRIDE + cg*16) = v;
                    }
                }
            }
            __syncthreads();

            uint32_t aBase = aLane + kx*ASTRIDE;
#pragma unroll
            for (int ks = 0; ks < 8; ks++) {
                uint32_t ah[2][4], al[2][4], bq[6][4];
                ldsm4(ah[0], aBase + ks*32);
                ldsm4(ah[1], aBase + 16*ASTRIDE + ks*32);
                ldsm4(al[0], aBase + A_SPLIT + ks*32);
                ldsm4(al[1], aBase + A_SPLIT + 16*ASTRIDE + ks*32);
#pragma unroll
                for (int nt = 0; nt < 6; nt++)
                    ldsm4(bq[nt], bLane + nt*16*ASTRIDE + ks*32);
#pragma unroll
                for (int mi = 0; mi < 2; mi++)
#pragma unroll
                    for (int nj = 0; nj < 12; nj++)
                        mma16816(acc[mi][nj], ah[mi], &bq[nj >> 1][(nj & 1)*2]);
#pragma unroll
                for (int mi = 0; mi < 2; mi++)
#pragma unroll
                    for (int nj = 0; nj < 12; nj++)
                        mma16816(acc[mi][nj], al[mi], &bq[nj >> 1][(nj & 1)*2]);
#pragma unroll
                for (int nt = 0; nt < 6; nt++)
                    ldsm4(bq[nt], bLane + B_SPLIT + nt*16*ASTRIDE + ks*32);
#pragma unroll
                for (int mi = 0; mi < 2; mi++)
#pragma unroll
                    for (int nj = 0; nj < 12; nj++)
                        mma16816(acc[mi][nj], ah[mi], &bq[nj >> 1][(nj & 1)*2]);
            }
        }
    }

    // ---- epilogue: accs -> f32 smem [128 px][192 oc], fused GRU ----
    __syncthreads();
    {
        float* bufp = (float*)smem;
        int r0 = lane >> 2, c0 = (lane & 3)*2;
#pragma unroll
        for (int mi = 0; mi < 2; mi++) {
#pragma unroll
            for (int nj = 0; nj < 12; nj++) {
                int px = warp_m*32 + mi*16 + r0;
                int oc = warp_n*96 + nj*8 + c0;
                float* s0 = bufp + px*GRU_STRIDE + oc;
                s0[0] = acc[mi][nj][0];
                s0[1] = acc[mi][nj][1];
                float* s1 = bufp + (px + 8)*GRU_STRIDE + oc;
                s1[0] = acc[mi][nj][2];
                s1[1] = acc[mi][nj][3];
            }
        }
    }
    __syncthreads();
    {
        const float* bufp = (const float*)smem;
        int px = tid & 127, half = tid >> 7;
        const float* row = bufp + px*GRU_STRIDE;
        float hv[32];
#pragma unroll
        for (int k = 0; k < 32; k++) {
            int c = half*32 + k;
            float xr = row[c]        + bxv[c]        + bhv[c];
            float xz = row[64 + c]   + bxv[64 + c]   + bhv[64 + c];
            float xn = row[128 + c]  + bxv[128 + c];
            float rg = 1.f / (1.f + expf(-xr));
            float zg = 1.f / (1.f + expf(-xz));
            float ng = tanhf(xn + rg * bhv[128 + c]);
            hv[k] = (1.f - zg) * ng;
        }
        if (last) {
            float* dst = ext_out + (size_t)img*CHW + h*WW + px;
#pragma unroll
            for (int k = 0; k < 32; k++)
                dst[(size_t)(half*32 + k) * HWSZ] = hv[k];
        } else {
            uint32_t hw[16], lw[16];
#pragma unroll
            for (int g = 0; g < 16; g++) {
                float a = hv[2*g], b2 = hv[2*g + 1];
                __nv_bfloat162 hb = __floats2bfloat162_rn(a, b2);
                float2 hf = __bfloat1622float2(hb);
                __nv_bfloat162 lb = __floats2bfloat162_rn(a - hf.x, b2 - hf.y);
                hw[g] = *(uint32_t*)&hb;
                lw[g] = *(uint32_t*)&lb;
            }
            int nb = buf ^ 1;
            int wordb = ((h + 1)*PW + (px + 1)) * 64 + half*16;
            uint32_t* Ph = (uint32_t*)&g_X[0][nb][img][0] + wordb;
            uint32_t* Pl = (uint32_t*)&g_X[1][nb][img][0] + wordb;
#pragma unroll
            for (int g4 = 0; g4 < 4; g4++) {
                *(uint4*)(Ph + g4*4) = make_uint4(hw[4*g4], hw[4*g4+1], hw[4*g4+2], hw[4*g4+3]);
                *(uint4*)(Pl + g4*4) = make_uint4(lw[4*g4], lw[4*g4+1], lw[4*g4+2], lw[4*g4+3]);
            }
        }
    }
}

// ---------------------------------------------------------------------------
extern "C" void kernel_launch(void* const* d_in, const int* in_sizes, int n_in,
                              void* d_out, int out_size)
{
    const float* feats = (const float*)d_in[0];
    const float* trans = (const float*)d_in[1];
    const float* wx    = (const float*)d_in[2];
    // d_in[3] = wh : unused (h0 = 0)
    const float* bx    = (const float*)d_in[4];
    const float* bh    = (const float*)d_in[5];
    float* out = (float*)d_out;

    cudaFuncSetAttribute(conv_mma_kernel,
                         cudaFuncAttributeMaxDynamicSharedMemorySize, SMEM_CONV);

    wprep_kernel<<<(2*9*OC*IC + 255)/256, 256>>>(wx);
    border_kernel<<<NIMG, 256>>>();
    pack0_kernel<<<dim3(WW/32, HH, NIMG), 256>>>(feats);

    for (int it = 0; it < ITERS; it++) {
        warp_mean_kernel<<<dim3(WW/4, HH/2, NIMG), 256>>>(trans, it);
        conv_mma_kernel<<<dim3(HH, NIMG), 256, SMEM_CONV>>>(
            bx, bh, out, it, (it == ITERS-1) ? 1 : 0);
    }
}

// round 11
// speedup vs baseline: 4.0320x; 1.2912x over previous
#include <cuda_runtime.h>
#include <cuda_bf16.h>
#include <math.h>
#include <stdint.h>

#define AG   5
#define BB   2
#define CC   64
#define HH   128
#define WW   128
#define HWSZ (HH*WW)          // 16384
#define CHW  (CC*HWSZ)        // 1048576
#define NIMG (BB*AG)          // 10
#define OC   192
#define IC   128
#define ITERS 2
#define PW   130              // padded H/W
#define PPIX (PW*PW)          // 16900

// ---------------- device scratch (no allocs allowed) ----------------
// g_X[split][buf][img][pix*128ch] : padded NHWC bf16. ch0-63 = feats, ch64-127 = mean.
__device__ __nv_bfloat16 g_X[2][2][NIMG][(size_t)PPIX*IC];   // 173 MB
__device__ float g_F[2][NIMG][(size_t)HWSZ*CC];              // 84 MB fp32 NHWC feats (for warp gathers)
__device__ __nv_bfloat16 g_W2[2][9][OC*IC];                  // weights, oc' = 3*c + gate permuted

// ---------------- helpers ----------------
__device__ __forceinline__ uint32_t smem_u32(const void* p) {
    uint32_t a;
    asm("{ .reg .u64 t; cvta.to.shared.u64 t, %1; cvt.u32.u64 %0, t; }" : "=r"(a) : "l"(p));
    return a;
}
__device__ __forceinline__ void ldsm4(uint32_t* r, uint32_t addr) {
    asm volatile("ldmatrix.sync.aligned.m8n8.x4.shared.b16 {%0,%1,%2,%3}, [%4];"
        : "=r"(r[0]), "=r"(r[1]), "=r"(r[2]), "=r"(r[3]) : "r"(addr));
}
__device__ __forceinline__ void ldsm2(uint32_t* r, uint32_t addr) {
    asm volatile("ldmatrix.sync.aligned.m8n8.x2.shared.b16 {%0,%1}, [%2];"
        : "=r"(r[0]), "=r"(r[1]) : "r"(addr));
}
__device__ __forceinline__ void mma16816(float* c, const uint32_t* a, const uint32_t* b) {
    asm volatile("mma.sync.aligned.m16n8k16.row.col.f32.bf16.bf16.f32 "
        "{%0,%1,%2,%3}, {%4,%5,%6,%7}, {%8,%9}, {%0,%1,%2,%3};"
        : "+f"(c[0]), "+f"(c[1]), "+f"(c[2]), "+f"(c[3])
        : "r"(a[0]), "r"(a[1]), "r"(a[2]), "r"(a[3]), "r"(b[0]), "r"(b[1]));
}
#define CP16(dst, src) \
    asm volatile("cp.async.cg.shared.global [%0], [%1], 16;" :: "r"(dst), "l"(src))
#define CPWAIT() \
    asm volatile("cp.async.commit_group;\n\tcp.async.wait_group 0;" ::: "memory")

// smem geometry for conv kernel
#define ASTRIDE   272                 // 128 bf16 + 16B pad (16B-aligned, odd*16 -> no ldsm conflicts)
#define A_SPLIT   35360               // 130 * 272
#define OFF_B     70720               // 2 * A_SPLIT
#define B_SPLIT   13056               // 48 * 272
#define SMEM_CONV 96832               // OFF_B + 2*B_SPLIT  -> 2 CTAs/SM
#define GRU_STRIDE 49

// ---------------------------------------------------------------------------
// Kernel 1: warp-per-pixel fused double-bilinear warp + masked mean.
// Gathers fp32 NHWC (g_F): one LDG.64 per gather point per lane.
// Writes mean into g_X[.][buf] channels 64-127 as bf16 hi/lo.
// ---------------------------------------------------------------------------
__global__ __launch_bounds__(256) void warp_mean_kernel(
    const float* __restrict__ trans, int buf)
{
    int tid = threadIdx.x, wid = tid >> 5, lane = tid & 31;
    int img = blockIdx.z;
    int b = img / AG, i = img % AG;
    int w = blockIdx.x * 4 + (wid & 3);
    int h = blockIdx.y * 2 + (wid >> 2);

    float2 acc = make_float2(0.f, 0.f);

    for (int j = 0; j < AG; j++) {
        if (j == i) continue;
        const float2* Pf = (const float2*)&g_F[buf][b*AG + j][0];

        const float* tp = trans + (((b*AG + i)*AG + j) << 4);
        float t00 = tp[0], t01 = tp[1], t03 = tp[3];
        float t10 = tp[4], t11 = tp[5], t13 = tp[7];

        float sx = 2.f * t03, sy = -2.f * t13;
        float fsx = floorf(sx), fsy = floorf(sy);
        float axf = sx - fsx, ayf = sy - fsy;
        int qx0 = w + (int)fsx, qy0 = h + (int)fsy;

        // lane k (0-15, duplicated on 16-31) computes gather point k
        int k  = lane & 15;
        int a2 = (k >> 3) & 1, b2 = (k >> 2) & 1, u = (k >> 1) & 1, v = k & 1;
        int p = qy0 + a2, q = qx0 + b2;
        bool outerOK = (p >= 0) && (p < HH) && (q >= 0) && (q < WW);
        float ow = (a2 ? ayf : 1.f - ayf) * (b2 ? axf : 1.f - axf);
        float gxq = (float)(2*q + 1) * (1.f/(float)WW) - 1.f;
        float gyp = (float)(2*p + 1) * (1.f/(float)HH) - 1.f;
        float px = t00*gxq + t01*gyp;
        float py = t10*gxq + t11*gyp;
        float xs = ((px + 1.f)*(float)WW - 1.f)*0.5f;
        float ys = ((py + 1.f)*(float)HH - 1.f)*0.5f;
        float xs0 = floorf(xs), ys0 = floorf(ys);
        float bx1 = xs - xs0, by1 = ys - ys0;
        int X = (int)xs0 + v, Y = (int)ys0 + u;
        bool ok = outerOK && (X >= 0) && (X < WW) && (Y >= 0) && (Y < HH);
        float iw = (u ? by1 : 1.f - by1) * (v ? bx1 : 1.f - bx1);
        float wt = ok ? (ow * iw) : 0.f;
        int Yc = min(max(Y, 0), HH-1), Xc = min(max(X, 0), WW-1);
        int offw = (Yc*WW + Xc) * 32;   // float2 offset of pixel (32 float2 = 64 ch)

#pragma unroll
        for (int kk = 0; kk < 16; kk++) {
            float wtk = __shfl_sync(0xffffffffu, wt, kk);
            int   ofk = __shfl_sync(0xffffffffu, offw, kk);
            if (wtk != 0.f) {
                float2 v2 = Pf[ofk + lane];
                acc.x = fmaf(wtk, v2.x, acc.x);
                acc.y = fmaf(wtk, v2.y, acc.y);
            }
        }
    }

    acc.x *= 0.25f; acc.y *= 0.25f;
    __nv_bfloat162 hb = __floats2bfloat162_rn(acc.x, acc.y);
    float2 hf = __bfloat1622float2(hb);
    __nv_bfloat162 lb = __floats2bfloat162_rn(acc.x - hf.x, acc.y - hf.y);
    int dpix = ((h + 1)*PW + (w + 1)) * 64 + 32 + lane;   // mean half: words 32-63
    ((uint32_t*)&g_X[0][buf][img][0])[dpix] = *(uint32_t*)&hb;
    ((uint32_t*)&g_X[1][buf][img][0])[dpix] = *(uint32_t*)&lb;
}

// ---------------------------------------------------------------------------
// Weight prepack: wx[oc][cin][3][3] fp32 -> g_W2[split][tap][oc'][cin] bf16,
// oc' = 3*c + gate  (orig oc = gate*64 + c) so 48-row groups = 16 channel triplets
// ---------------------------------------------------------------------------
__global__ __launch_bounds__(256) void wprep_kernel(const float* __restrict__ wx)
{
    int idx = blockIdx.x * 256 + threadIdx.x;
    if (idx >= 2*9*OC*IC) return;
    int s   = idx / (9*OC*IC);
    int r1  = idx % (9*OC*IC);
    int tap = r1 / (OC*IC);
    int r2  = r1 % (OC*IC);
    int oc  = r2 / IC;
    int cin = r2 % IC;
    float v = wx[(size_t)(oc*IC + cin)*9 + tap];
    __nv_bfloat16 hi = __float2bfloat16_rn(v);
    __nv_bfloat16 o  = (s == 0) ? hi : __float2bfloat16_rn(v - __bfloat162float(hi));
    int gate = oc / CC, c = oc % CC;
    g_W2[s][tap][(c*3 + gate)*IC + cin] = o;
}

// ---------------------------------------------------------------------------
// Zero the 1-px border of both g_X buffers
// ---------------------------------------------------------------------------
__global__ void border_kernel()
{
    int img = blockIdx.x;
    uint4 z = make_uint4(0,0,0,0);
    for (int p = threadIdx.x; p < PPIX; p += blockDim.x) {
        int r = p / PW, c = p % PW;
        if (r == 0 || r == PW-1 || c == 0 || c == PW-1) {
#pragma unroll
            for (int s = 0; s < 2; s++)
#pragma unroll
                for (int bf = 0; bf < 2; bf++) {
                    uint4* d = (uint4*)&g_X[s][bf][img][(size_t)p*IC];
#pragma unroll
                    for (int k2 = 0; k2 < 16; k2++) d[k2] = z;
                }
        }
    }
}

// ---------------------------------------------------------------------------
// One-time pack: input feats NCHW fp32 -> g_X[.][0] hi/lo + g_F[0] fp32 NHWC
// ---------------------------------------------------------------------------
__global__ __launch_bounds__(256) void pack0_kernel(const float* __restrict__ feats)
{
    __shared__ float s[CC][33];
    int img = blockIdx.z, h = blockIdx.y, w0 = blockIdx.x * 32;
    int tid = threadIdx.x;
    const float* f0 = feats + (size_t)img * CHW;
#pragma unroll
    for (int pass = 0; pass < 8; pass++) {
        int c = pass*8 + (tid >> 5);
        s[c][tid & 31] = f0[(size_t)c*HWSZ + h*WW + w0 + (tid & 31)];
    }
    __syncthreads();
    int px = tid >> 3;
    int c0 = (tid & 7) * 8;
    uint32_t uh[4], ul[4];
    float fv[8];
#pragma unroll
    for (int k = 0; k < 4; k++) {
        float v0 = s[c0 + 2*k][px], v1 = s[c0 + 2*k + 1][px];
        fv[2*k] = v0; fv[2*k+1] = v1;
        __nv_bfloat162 hb = __floats2bfloat162_rn(v0, v1);
        float2 hf = __bfloat1622float2(hb);
        __nv_bfloat162 lb = __floats2bfloat162_rn(v0 - hf.x, v1 - hf.y);
        uh[k] = *(uint32_t*)&hb;
        ul[k] = *(uint32_t*)&lb;
    }
    int wordb = ((h + 1)*PW + (w0 + px + 1)) * 64 + (c0 >> 1);
    *(uint4*)((uint32_t*)&g_X[0][0][img][0] + wordb) = make_uint4(uh[0], uh[1], uh[2], uh[3]);
    *(uint4*)((uint32_t*)&g_X[1][0][img][0] + wordb) = make_uint4(ul[0], ul[1], ul[2], ul[3]);
    float* fd = &g_F[0][img][(size_t)(h*WW + w0 + px)*CC + c0];
    *(float4*)fd       = make_float4(fv[0], fv[1], fv[2], fv[3]);
    *(float4*)(fd + 4) = make_float4(fv[4], fv[5], fv[6], fv[7]);
}

// ---------------------------------------------------------------------------
// Conv+GRU via mma.sync (HMMA bf16, 3-term hi/lo split). 2 CTAs/SM.
// CTA = (row h, oc'-group g of 48 = 16 channel triplets, img).
// M=128 px, N=48 oc', K=9 taps x 128 cin. 8 warps = 4(M) x 2(N=24).
// Epilogue: fused GRU -> ext_out (last) or g_X[.][buf^1] + g_F[buf^1].
// ---------------------------------------------------------------------------
__global__ __launch_bounds__(256, 2) void conv_mma_kernel(
    const float* __restrict__ bxv, const float* __restrict__ bhv,
    float* __restrict__ ext_out, int buf, int last)
{
    extern __shared__ char smem[];
    uint32_t sb = smem_u32(smem);
    int tid = threadIdx.x, wid = tid >> 5, lane = tid & 31;
    int img = blockIdx.z, h = blockIdx.x, grp = blockIdx.y;
    int warp_m = wid & 3, warp_n = wid >> 2;

    float acc[2][3][4];
#pragma unroll
    for (int mi = 0; mi < 2; mi++)
#pragma unroll
        for (int nj = 0; nj < 3; nj++)
#pragma unroll
            for (int k = 0; k < 4; k++) acc[mi][nj][k] = 0.f;

    uint32_t aLane = sb + (uint32_t)(warp_m*32 + (lane & 15))*ASTRIDE + (lane >> 4)*16;
    uint32_t bx4 = sb + OFF_B
                 + (uint32_t)(warp_n*24 + (lane & 7) + ((lane >> 4) << 3))*ASTRIDE
                 + ((lane >> 3) & 1)*16;
    uint32_t bx2 = sb + OFF_B
                 + (uint32_t)(warp_n*24 + 16 + (lane & 7))*ASTRIDE
                 + (((lane >> 3) & 1) & 1)*16;

    for (int ky = 0; ky < 3; ky++) {
        __syncthreads();   // previous consumers of A & B done
        // stage A row (h+ky): 130 px x 128 cin, hi & lo (cp.async)
#pragma unroll
        for (int s = 0; s < 2; s++) {
            const __nv_bfloat16* src = &g_X[s][buf][img][((size_t)(h + ky)*PW)*IC];
            for (int idx = tid; idx < 130*16; idx += 256) {
                int p = idx >> 4, cg = idx & 15;
                CP16(sb + s*A_SPLIT + p*ASTRIDE + cg*16, src + p*IC + cg*8);
            }
        }
        for (int kx = 0; kx < 3; kx++) {
            if (kx > 0) __syncthreads();   // previous B consumers done
            {
                int tap = ky*3 + kx;
#pragma unroll
                for (int s = 0; s < 2; s++) {
                    const __nv_bfloat16* src = &g_W2[s][tap][(size_t)(grp*48)*IC];
                    for (int idx = tid; idx < 48*16; idx += 256) {
                        int p = idx >> 4, cg = idx & 15;
                        CP16(sb + OFF_B + s*B_SPLIT + p*ASTRIDE + cg*16, src + p*IC + cg*8);
                    }
                }
            }
            CPWAIT();
            __syncthreads();

            uint32_t aBase = aLane + kx*ASTRIDE;
#pragma unroll
            for (int ks = 0; ks < 8; ks++) {
                uint32_t ah[2][4], al[2][4], bh4[4], bh2[2], bl4[4], bl2[2];
                ldsm4(ah[0], aBase + ks*32);
                ldsm4(ah[1], aBase + 16*ASTRIDE + ks*32);
                ldsm4(al[0], aBase + A_SPLIT + ks*32);
                ldsm4(al[1], aBase + A_SPLIT + 16*ASTRIDE + ks*32);
                ldsm4(bh4, bx4 + ks*32);
                ldsm2(bh2, bx2 + ks*32);
                ldsm4(bl4, bx4 + B_SPLIT + ks*32);
                ldsm2(bl2, bx2 + B_SPLIT + ks*32);
#pragma unroll
                for (int mi = 0; mi < 2; mi++) {
                    mma16816(acc[mi][0], ah[mi], &bh4[0]);
                    mma16816(acc[mi][1], ah[mi], &bh4[2]);
                    mma16816(acc[mi][2], ah[mi], bh2);
                }
#pragma unroll
                for (int mi = 0; mi < 2; mi++) {
                    mma16816(acc[mi][0], al[mi], &bh4[0]);
                    mma16816(acc[mi][1], al[mi], &bh4[2]);
                    mma16816(acc[mi][2], al[mi], bh2);
                }
#pragma unroll
                for (int mi = 0; mi < 2; mi++) {
                    mma16816(acc[mi][0], ah[mi], &bl4[0]);
                    mma16816(acc[mi][1], ah[mi], &bl4[2]);
                    mma16816(acc[mi][2], ah[mi], bl2);
                }
            }
        }
    }

    // ---- epilogue: accs -> f32 smem [128 px][48 oc'], fused GRU ----
    __syncthreads();
    {
        float* bufp = (float*)smem;
        int r0 = lane >> 2, c0r = (lane & 3)*2;
#pragma unroll
        for (int mi = 0; mi < 2; mi++) {
#pragma unroll
            for (int nj = 0; nj < 3; nj++) {
                int px = warp_m*32 + mi*16 + r0;
                int oc = warp_n*24 + nj*8 + c0r;
                float* s0 = bufp + px*GRU_STRIDE + oc;
                s0[0] = acc[mi][nj][0];
                s0[1] = acc[mi][nj][1];
                float* s1 = bufp + (px + 8)*GRU_STRIDE + oc;
                s1[0] = acc[mi][nj][2];
                s1[1] = acc[mi][nj][3];
            }
        }
    }
    __syncthreads();
    {
        const float* bufp = (const float*)smem;
        int px = tid & 127, half = tid >> 7;
        const float* row = bufp + px*GRU_STRIDE + half*24;
        int Cbase = grp*16 + half*8;
        float hv[8];
#pragma unroll
        for (int c = 0; c < 8; c++) {
            int C = Cbase + c;
            float xr = row[c*3 + 0] + bxv[C]       + bhv[C];
            float xz = row[c*3 + 1] + bxv[64 + C]  + bhv[64 + C];
            float xn = row[c*3 + 2] + bxv[128 + C];
            float rg = 1.f / (1.f + expf(-xr));
            float zg = 1.f / (1.f + expf(-xz));
            float ng = tanhf(xn + rg * bhv[128 + C]);
            hv[c] = (1.f - zg) * ng;
        }
        if (last) {
            float* dst = ext_out + (size_t)img*CHW + h*WW + px;
#pragma unroll
            for (int c = 0; c < 8; c++)
                dst[(size_t)(Cbase + c) * HWSZ] = hv[c];
        } else {
            uint32_t hw[4], lw[4];
#pragma unroll
            for (int g2 = 0; g2 < 4; g2++) {
                float a = hv[2*g2], b2 = hv[2*g2 + 1];
                __nv_bfloat162 hb = __floats2bfloat162_rn(a, b2);
                float2 hf = __bfloat1622float2(hb);
                __nv_bfloat162 lb = __floats2bfloat162_rn(a - hf.x, b2 - hf.y);
                hw[g2] = *(uint32_t*)&hb;
                lw[g2] = *(uint32_t*)&lb;
            }
            int nb = buf ^ 1;
            int wordb = ((h + 1)*PW + (px + 1)) * 64 + (Cbase >> 1);
            *(uint4*)((uint32_t*)&g_X[0][nb][img][0] + wordb) = make_uint4(hw[0], hw[1], hw[2], hw[3]);
            *(uint4*)((uint32_t*)&g_X[1][nb][img][0] + wordb) = make_uint4(lw[0], lw[1], lw[2], lw[3]);
            float* fd = &g_F[nb][img][(size_t)(h*WW + px)*CC + Cbase];
            *(float4*)fd       = make_float4(hv[0], hv[1], hv[2], hv[3]);
            *(float4*)(fd + 4) = make_float4(hv[4], hv[5], hv[6], hv[7]);
        }
    }
}

// ---------------------------------------------------------------------------
extern "C" void kernel_launch(void* const* d_in, const int* in_sizes, int n_in,
                              void* d_out, int out_size)
{
    const float* feats = (const float*)d_in[0];
    const float* trans = (const float*)d_in[1];
    const float* wx    = (const float*)d_in[2];
    // d_in[3] = wh : unused (h0 = 0)
    const float* bx    = (const float*)d_in[4];
    const float* bh    = (const float*)d_in[5];
    float* out = (float*)d_out;

    cudaFuncSetAttribute(conv_mma_kernel,
                         cudaFuncAttributeMaxDynamicSharedMemorySize, SMEM_CONV);

    wprep_kernel<<<(2*9*OC*IC + 255)/256, 256>>>(wx);
    border_kernel<<<NIMG, 256>>>();
    pack0_kernel<<<dim3(WW/32, HH, NIMG), 256>>>(feats);

    for (int it = 0; it < ITERS; it++) {
        warp_mean_kernel<<<dim3(WW/4, HH/2, NIMG), 256>>>(trans, it);
        conv_mma_kernel<<<dim3(HH, 4, NIMG), 256, SMEM_CONV>>>(
            bx, bh, out, it, (it == ITERS-1) ? 1 : 0);
    }
}

// round 12
// speedup vs baseline: 4.3033x; 1.0673x over previous
#include <cuda_runtime.h>
#include <cuda_bf16.h>
#include <math.h>
#include <stdint.h>

#define AG   5
#define BB   2
#define CC   64
#define HH   128
#define WW   128
#define HWSZ (HH*WW)          // 16384
#define CHW  (CC*HWSZ)        // 1048576
#define NIMG (BB*AG)          // 10
#define OC   192
#define IC   128
#define ITERS 2
#define PW   130              // padded H/W
#define PPIX (PW*PW)          // 16900
#define NPAIR 40              // BB * AG * (AG-1)

// ---------------- device scratch (no allocs allowed) ----------------
// g_X[split][buf][img][pix*128ch] : padded NHWC bf16. ch0-63 = feats, ch64-127 = mean.
__device__ __nv_bfloat16 g_X[2][2][NIMG][(size_t)PPIX*IC];   // 173 MB
__device__ float g_F[2][NIMG][(size_t)HWSZ*CC];              // 84 MB fp32 NHWC feats
__device__ float g_R[NPAIR][(size_t)HWSZ*CC];                // 168 MB rotation fields
__device__ __nv_bfloat16 g_W2[2][9][OC*IC];                  // weights, oc' = 3*c + gate

// ---------------- helpers ----------------
__device__ __forceinline__ uint32_t smem_u32(const void* p) {
    uint32_t a;
    asm("{ .reg .u64 t; cvta.to.shared.u64 t, %1; cvt.u32.u64 %0, t; }" : "=r"(a) : "l"(p));
    return a;
}
__device__ __forceinline__ void ldsm4(uint32_t* r, uint32_t addr) {
    asm volatile("ldmatrix.sync.aligned.m8n8.x4.shared.b16 {%0,%1,%2,%3}, [%4];"
        : "=r"(r[0]), "=r"(r[1]), "=r"(r[2]), "=r"(r[3]) : "r"(addr));
}
__device__ __forceinline__ void ldsm2(uint32_t* r, uint32_t addr) {
    asm volatile("ldmatrix.sync.aligned.m8n8.x2.shared.b16 {%0,%1}, [%2];"
        : "=r"(r[0]), "=r"(r[1]) : "r"(addr));
}
__device__ __forceinline__ void mma16816(float* c, const uint32_t* a, const uint32_t* b) {
    asm volatile("mma.sync.aligned.m16n8k16.row.col.f32.bf16.bf16.f32 "
        "{%0,%1,%2,%3}, {%4,%5,%6,%7}, {%8,%9}, {%0,%1,%2,%3};"
        : "+f"(c[0]), "+f"(c[1]), "+f"(c[2]), "+f"(c[3])
        : "r"(a[0]), "r"(a[1]), "r"(a[2]), "r"(a[3]), "r"(b[0]), "r"(b[1]));
}
#define CP16(dst, src) \
    asm volatile("cp.async.cg.shared.global [%0], [%1], 16;" :: "r"(dst), "l"(src))
#define CP_COMMIT() asm volatile("cp.async.commit_group;" ::: "memory")
#define CP_WAIT1()  asm volatile("cp.async.wait_group 1;" ::: "memory")

// smem geometry for conv kernel (swizzled 256B rows, no padding)
#define A_SPLIT   33280               // 130 * 256
#define OFF_B     66560               // 2 * A_SPLIT
#define B_SPLIT   12288               // 48 * 256
#define B_PAIR    24576               // hi+lo
#define SMEM_CONV 115712              // OFF_B + 2*B_PAIR -> 2 CTAs/SM (with 1KB reserve)
#define GRU_STRIDE 49

// ---------------------------------------------------------------------------
// Pass 1: rotation field. One field per (b,i,j!=i) pair: R = bilinear rotation
// resample of feats[b,j] at integer pixels. Warp per pixel, lane = ch pair.
// ---------------------------------------------------------------------------
__global__ __launch_bounds__(256) void rot_kernel(const float* __restrict__ trans, int buf)
{
    int tid = threadIdx.x, wid = tid >> 5, lane = tid & 31;
    int f = blockIdx.z;
    int b = f / 20, r = f % 20, i = r / 4, jj = r % 4;
    int j = jj + (jj >= i);
    int w = blockIdx.x * 4 + (wid & 3);
    int h = blockIdx.y * 2 + (wid >> 2);

    const float2* Pf = (const float2*)&g_F[buf][b*AG + j][0];
    const float* tp = trans + (((b*AG + i)*AG + j) << 4);
    float t00 = tp[0], t01 = tp[1], t10 = tp[4], t11 = tp[5];

    float gxq = (float)(2*w + 1) * (1.f/(float)WW) - 1.f;
    float gyp = (float)(2*h + 1) * (1.f/(float)HH) - 1.f;
    float px = t00*gxq + t01*gyp;
    float py = t10*gxq + t11*gyp;
    float xs = ((px + 1.f)*(float)WW - 1.f)*0.5f;
    float ys = ((py + 1.f)*(float)HH - 1.f)*0.5f;
    float xs0 = floorf(xs), ys0 = floorf(ys);
    float bx1 = xs - xs0, by1 = ys - ys0;
    int k = lane & 3;
    int u = (k >> 1) & 1, v = k & 1;
    int X = (int)xs0 + v, Y = (int)ys0 + u;
    bool ok = (X >= 0) && (X < WW) && (Y >= 0) && (Y < HH);
    float iw = (u ? by1 : 1.f - by1) * (v ? bx1 : 1.f - bx1);
    float wt = ok ? iw : 0.f;
    int Yc = min(max(Y, 0), HH-1), Xc = min(max(X, 0), WW-1);
    int offw = (Yc*WW + Xc) * 32;

    float2 acc = make_float2(0.f, 0.f);
#pragma unroll
    for (int kk = 0; kk < 4; kk++) {
        float wtk = __shfl_sync(0xffffffffu, wt, kk);
        int   ofk = __shfl_sync(0xffffffffu, offw, kk);
        if (wtk != 0.f) {
            float2 v2 = Pf[ofk + lane];
            acc.x = fmaf(wtk, v2.x, acc.x);
            acc.y = fmaf(wtk, v2.y, acc.y);
        }
    }
    float2* dst = (float2*)&g_R[f][(size_t)(h*WW + w)*CC];
    dst[lane] = acc;
}

// ---------------------------------------------------------------------------
// Pass 2: translate + masked mean over j != i. Uniform per-warp R reads.
// Writes mean into g_X[.][buf] channels 64-127 as bf16 hi/lo.
// ---------------------------------------------------------------------------
__global__ __launch_bounds__(256) void mean_kernel(const float* __restrict__ trans, int buf)
{
    int tid = threadIdx.x, wid = tid >> 5, lane = tid & 31;
    int img = blockIdx.z;
    int b = img / AG, i = img % AG;
    int w = blockIdx.x * 4 + (wid & 3);
    int h = blockIdx.y * 2 + (wid >> 2);

    float2 acc = make_float2(0.f, 0.f);
#pragma unroll
    for (int jj = 0; jj < 4; jj++) {
        int j = jj + (jj >= i);
        int f = b*20 + i*4 + jj;
        const float* tp = trans + (((b*AG + i)*AG + j) << 4);
        float sx = 2.f * tp[3], sy = -2.f * tp[7];
        float fsx = floorf(sx), fsy = floorf(sy);
        float ax = sx - fsx, ay = sy - fsy;
        int qx0 = w + (int)fsx, qy0 = h + (int)fsy;
        const float2* R = (const float2*)&g_R[f][0];
#pragma unroll
        for (int a2 = 0; a2 < 2; a2++) {
            int p = qy0 + a2;
            if ((unsigned)p < (unsigned)HH) {
                float wy = a2 ? ay : 1.f - ay;
#pragma unroll
                for (int b2 = 0; b2 < 2; b2++) {
                    int q = qx0 + b2;
                    if ((unsigned)q < (unsigned)WW) {
                        float ww = wy * (b2 ? ax : 1.f - ax);
                        float2 v2 = R[(size_t)(p*WW + q)*32 + lane];
                        acc.x = fmaf(ww, v2.x, acc.x);
                        acc.y = fmaf(ww, v2.y, acc.y);
                    }
                }
            }
        }
    }

    acc.x *= 0.25f; acc.y *= 0.25f;
    __nv_bfloat162 hb = __floats2bfloat162_rn(acc.x, acc.y);
    float2 hf = __bfloat1622float2(hb);
    __nv_bfloat162 lb = __floats2bfloat162_rn(acc.x - hf.x, acc.y - hf.y);
    int dpix = ((h + 1)*PW + (w + 1)) * 64 + 32 + lane;
    ((uint32_t*)&g_X[0][buf][img][0])[dpix] = *(uint32_t*)&hb;
    ((uint32_t*)&g_X[1][buf][img][0])[dpix] = *(uint32_t*)&lb;
}

// ---------------------------------------------------------------------------
// Weight prepack: wx[oc][cin][3][3] fp32 -> g_W2[split][tap][oc'][cin] bf16,
// oc' = 3*c + gate  (orig oc = gate*64 + c)
// ---------------------------------------------------------------------------
__global__ __launch_bounds__(256) void wprep_kernel(const float* __restrict__ wx)
{
    int idx = blockIdx.x * 256 + threadIdx.x;
    if (idx >= 2*9*OC*IC) return;
    int s   = idx / (9*OC*IC);
    int r1  = idx % (9*OC*IC);
    int tap = r1 / (OC*IC);
    int r2  = r1 % (OC*IC);
    int oc  = r2 / IC;
    int cin = r2 % IC;
    float v = wx[(size_t)(oc*IC + cin)*9 + tap];
    __nv_bfloat16 hi = __float2bfloat16_rn(v);
    __nv_bfloat16 o  = (s == 0) ? hi : __float2bfloat16_rn(v - __bfloat162float(hi));
    int gate = oc / CC, c = oc % CC;
    g_W2[s][tap][(c*3 + gate)*IC + cin] = o;
}

// ---------------------------------------------------------------------------
// Zero the 1-px border of both g_X buffers
// ---------------------------------------------------------------------------
__global__ void border_kernel()
{
    int img = blockIdx.x;
    uint4 z = make_uint4(0,0,0,0);
    for (int p = threadIdx.x; p < PPIX; p += blockDim.x) {
        int r = p / PW, c = p % PW;
        if (r == 0 || r == PW-1 || c == 0 || c == PW-1) {
#pragma unroll
            for (int s = 0; s < 2; s++)
#pragma unroll
                for (int bf = 0; bf < 2; bf++) {
                    uint4* d = (uint4*)&g_X[s][bf][img][(size_t)p*IC];
#pragma unroll
                    for (int k2 = 0; k2 < 16; k2++) d[k2] = z;
                }
        }
    }
}

// ---------------------------------------------------------------------------
// One-time pack: input feats NCHW fp32 -> g_X[.][0] hi/lo + g_F[0] fp32 NHWC
// ---------------------------------------------------------------------------
__global__ __launch_bounds__(256) void pack0_kernel(const float* __restrict__ feats)
{
    __shared__ float s[CC][33];
    int img = blockIdx.z, h = blockIdx.y, w0 = blockIdx.x * 32;
    int tid = threadIdx.x;
    const float* f0 = feats + (size_t)img * CHW;
#pragma unroll
    for (int pass = 0; pass < 8; pass++) {
        int c = pass*8 + (tid >> 5);
        s[c][tid & 31] = f0[(size_t)c*HWSZ + h*WW + w0 + (tid & 31)];
    }
    __syncthreads();
    int px = tid >> 3;
    int c0 = (tid & 7) * 8;
    uint32_t uh[4], ul[4];
    float fv[8];
#pragma unroll
    for (int k = 0; k < 4; k++) {
        float v0 = s[c0 + 2*k][px], v1 = s[c0 + 2*k + 1][px];
        fv[2*k] = v0; fv[2*k+1] = v1;
        __nv_bfloat162 hb = __floats2bfloat162_rn(v0, v1);
        float2 hf = __bfloat1622float2(hb);
        __nv_bfloat162 lb = __floats2bfloat162_rn(v0 - hf.x, v1 - hf.y);
        uh[k] = *(uint32_t*)&hb;
        ul[k] = *(uint32_t*)&lb;
    }
    int wordb = ((h + 1)*PW + (w0 + px + 1)) * 64 + (c0 >> 1);
    *(uint4*)((uint32_t*)&g_X[0][0][img][0] + wordb) = make_uint4(uh[0], uh[1], uh[2], uh[3]);
    *(uint4*)((uint32_t*)&g_X[1][0][img][0] + wordb) = make_uint4(ul[0], ul[1], ul[2], ul[3]);
    float* fd = &g_F[0][img][(size_t)(h*WW + w0 + px)*CC + c0];
    *(float4*)fd       = make_float4(fv[0], fv[1], fv[2], fv[3]);
    *(float4*)(fd + 4) = make_float4(fv[4], fv[5], fv[6], fv[7]);
}

// ---------------------------------------------------------------------------
// Conv staging (cp.async, XOR-swizzled 256B rows: chunk' = cg ^ (row&7))
// ---------------------------------------------------------------------------
__device__ __forceinline__ void stage_A(uint32_t sb, int img, int buf, int h, int ky, int tid)
{
#pragma unroll
    for (int s = 0; s < 2; s++) {
        const __nv_bfloat16* src = &g_X[s][buf][img][((size_t)(h + ky)*PW)*IC];
        for (int idx = tid; idx < 130*16; idx += 256) {
            int p = idx >> 4, cg = idx & 15;
            CP16(sb + s*A_SPLIT + p*256 + ((cg ^ (p & 7)) << 4), src + p*IC + cg*8);
        }
    }
}
__device__ __forceinline__ void stage_B(uint32_t sb, int grp, int tap, int tid)
{
    uint32_t base = sb + OFF_B + (uint32_t)(tap & 1)*B_PAIR;
#pragma unroll
    for (int s = 0; s < 2; s++) {
        const __nv_bfloat16* src = &g_W2[s][tap][(size_t)(grp*48)*IC];
        for (int idx = tid; idx < 48*16; idx += 256) {
            int n = idx >> 4, cg = idx & 15;
            CP16(base + s*B_SPLIT + n*256 + ((cg ^ (n & 7)) << 4), src + n*IC + cg*8);
        }
    }
}

// ---------------------------------------------------------------------------
// Conv+GRU via mma.sync (HMMA bf16, 3-term hi/lo split). 2 CTAs/SM.
// Double-buffered B prefetch via cp.async commit groups.
// CTA = (row h, oc'-group of 48, img). 8 warps = 4(M=32) x 2(N=24).
// ---------------------------------------------------------------------------
__global__ __launch_bounds__(256, 2) void conv_mma_kernel(
    const float* __restrict__ bxv, const float* __restrict__ bhv,
    float* __restrict__ ext_out, int buf, int last)
{
    extern __shared__ char smem[];
    uint32_t sb = smem_u32(smem);
    int tid = threadIdx.x, wid = tid >> 5, lane = tid & 31;
    int img = blockIdx.z, h = blockIdx.x, grp = blockIdx.y;
    int warp_m = wid & 3, warp_n = wid >> 2;

    float acc[2][3][4];
#pragma unroll
    for (int mi = 0; mi < 2; mi++)
#pragma unroll
        for (int nj = 0; nj < 3; nj++)
#pragma unroll
            for (int k = 0; k < 4; k++) acc[mi][nj][k] = 0.f;

    // per-lane constants
    int rowB4 = warp_n*24 + (lane & 7) + ((lane >> 4) << 3);
    int rowB2 = warp_n*24 + 16 + (lane & 7);
    int r7b   = lane & 7;
    int cselB = (lane >> 3) & 1;
    int hiA   = lane >> 4;

    // prologue: B[tap 0] into dbuf 0
    stage_B(sb, grp, 0, tid);
    CP_COMMIT();

    for (int ky = 0; ky < 3; ky++) {
        for (int kx = 0; kx < 3; kx++) {
            int tap = ky*3 + kx;
            __syncthreads();                 // prev consumers of A (ky) / B (tap-1 buffer) done
            if (kx == 0) { stage_A(sb, img, buf, h, ky, tid); CP_COMMIT(); }
            if (tap < 8) stage_B(sb, grp, tap + 1, tid);
            CP_COMMIT();
            CP_WAIT1();                      // all but newest group complete -> A(ky), B(tap) ready
            __syncthreads();

            uint32_t bb = sb + OFF_B + (uint32_t)(tap & 1)*B_PAIR;
            uint32_t b4base = bb + rowB4*256;
            uint32_t b2base = bb + rowB2*256;
            int rowA = warp_m*32 + kx + (lane & 15);
            uint32_t aBase = sb + rowA*256;
            int r7a = rowA & 7;

#pragma unroll
            for (int ks = 0; ks < 8; ks++) {
                uint32_t xA = (uint32_t)(((2*ks + hiA) ^ r7a) << 4);
                uint32_t xB = (uint32_t)(((2*ks + cselB) ^ r7b) << 4);
                uint32_t ah[2][4], al[2][4], bh4[4], bh2[2], bl4[4], bl2[2];
                ldsm4(ah[0], aBase + xA);
                ldsm4(ah[1], aBase + 4096 + xA);
                ldsm4(al[0], aBase + A_SPLIT + xA);
                ldsm4(al[1], aBase + A_SPLIT + 4096 + xA);
                ldsm4(bh4, b4base + xB);
                ldsm2(bh2, b2base + xB);
                ldsm4(bl4, b4base + B_SPLIT + xB);
                ldsm2(bl2, b2base + B_SPLIT + xB);
#pragma unroll
                for (int mi = 0; mi < 2; mi++) {
                    mma16816(acc[mi][0], ah[mi], &bh4[0]);
                    mma16816(acc[mi][1], ah[mi], &bh4[2]);
                    mma16816(acc[mi][2], ah[mi], bh2);
                }
#pragma unroll
                for (int mi = 0; mi < 2; mi++) {
                    mma16816(acc[mi][0], al[mi], &bh4[0]);
                    mma16816(acc[mi][1], al[mi], &bh4[2]);
                    mma16816(acc[mi][2], al[mi], bh2);
                }
#pragma unroll
                for (int mi = 0; mi < 2; mi++) {
                    mma16816(acc[mi][0], ah[mi], &bl4[0]);
                    mma16816(acc[mi][1], ah[mi], &bl4[2]);
                    mma16816(acc[mi][2], ah[mi], bl2);
                }
            }
        }
    }

    // ---- epilogue: accs -> f32 smem [128 px][48 oc'], fused GRU ----
    __syncthreads();
    {
        float* bufp = (float*)smem;
        int r0 = lane >> 2, c0r = (lane & 3)*2;
#pragma unroll
        for (int mi = 0; mi < 2; mi++) {
#pragma unroll
            for (int nj = 0; nj < 3; nj++) {
                int px = warp_m*32 + mi*16 + r0;
                int oc = warp_n*24 + nj*8 + c0r;
                float* s0 = bufp + px*GRU_STRIDE + oc;
                s0[0] = acc[mi][nj][0];
                s0[1] = acc[mi][nj][1];
                float* s1 = bufp + (px + 8)*GRU_STRIDE + oc;
                s1[0] = acc[mi][nj][2];
                s1[1] = acc[mi][nj][3];
            }
        }
    }
    __syncthreads();
    {
        const float* bufp = (const float*)smem;
        int px = tid & 127, half = tid >> 7;
        const float* row = bufp + px*GRU_STRIDE + half*24;
        int Cbase = grp*16 + half*8;
        float hv[8];
#pragma unroll
        for (int c = 0; c < 8; c++) {
            int C = Cbase + c;
            float xr = row[c*3 + 0] + bxv[C]       + bhv[C];
            float xz = row[c*3 + 1] + bxv[64 + C]  + bhv[64 + C];
            float xn = row[c*3 + 2] + bxv[128 + C];
            float rg = 1.f / (1.f + expf(-xr));
            float zg = 1.f / (1.f + expf(-xz));
            float ng = tanhf(xn + rg * bhv[128 + C]);
            hv[c] = (1.f - zg) * ng;
        }
        if (last) {
            float* dst = ext_out + (size_t)img*CHW + h*WW + px;
#pragma unroll
            for (int c = 0; c < 8; c++)
                dst[(size_t)(Cbase + c) * HWSZ] = hv[c];
        } else {
            uint32_t hw[4], lw[4];
#pragma unroll
            for (int g2 = 0; g2 < 4; g2++) {
                float a = hv[2*g2], b2 = hv[2*g2 + 1];
                __nv_bfloat162 hb = __floats2bfloat162_rn(a, b2);
                float2 hf = __bfloat1622float2(hb);
                __nv_bfloat162 lb = __floats2bfloat162_rn(a - hf.x, b2 - hf.y);
                hw[g2] = *(uint32_t*)&hb;
                lw[g2] = *(uint32_t*)&lb;
            }
            int nb = buf ^ 1;
            int wordb = ((h + 1)*PW + (px + 1)) * 64 + (Cbase >> 1);
            *(uint4*)((uint32_t*)&g_X[0][nb][img][0] + wordb) = make_uint4(hw[0], hw[1], hw[2], hw[3]);
            *(uint4*)((uint32_t*)&g_X[1][nb][img][0] + wordb) = make_uint4(lw[0], lw[1], lw[2], lw[3]);
            float* fd = &g_F[nb][img][(size_t)(h*WW + px)*CC + Cbase];
            *(float4*)fd       = make_float4(hv[0], hv[1], hv[2], hv[3]);
            *(float4*)(fd + 4) = make_float4(hv[4], hv[5], hv[6], hv[7]);
        }
    }
}

// ---------------------------------------------------------------------------
extern "C" void kernel_launch(void* const* d_in, const int* in_sizes, int n_in,
                              void* d_out, int out_size)
{
    const float* feats = (const float*)d_in[0];
    const float* trans = (const float*)d_in[1];
    const float* wx    = (const float*)d_in[2];
    // d_in[3] = wh : unused (h0 = 0)
    const float* bx    = (const float*)d_in[4];
    const float* bh    = (const float*)d_in[5];
    float* out = (float*)d_out;

    cudaFuncSetAttribute(conv_mma_kernel,
                         cudaFuncAttributeMaxDynamicSharedMemorySize, SMEM_CONV);
    cudaFuncSetAttribute(conv_mma_kernel,
                         cudaFuncAttributePreferredSharedMemoryCarveout, 100);

    wprep_kernel<<<(2*9*OC*IC + 255)/256, 256>>>(wx);
    border_kernel<<<NIMG, 256>>>();
    pack0_kernel<<<dim3(WW/32, HH, NIMG), 256>>>(feats);

    for (int it = 0; it < ITERS; it++) {
        rot_kernel<<<dim3(WW/4, HH/2, NPAIR), 256>>>(trans, it);
        mean_kernel<<<dim3(WW/4, HH/2, NIMG), 256>>>(trans, it);
        conv_mma_kernel<<<dim3(HH, 4, NIMG), 256, SMEM_CONV>>>(
            bx, bh, out, it, (it == ITERS-1) ? 1 : 0);
    }
}